// round 2
// baseline (speedup 1.0000x reference)
#include <cuda_runtime.h>

// POLLU RHS: dy[b, 0:20] = S @ flux(b), flux_r = k_r * C[a_r, b] * C[b_r, b]
// Fully unrolled stoichiometry; pure streaming kernel (320 MB traffic).

__global__ void __launch_bounds__(256) pollu_kernel(
    const float* __restrict__ C,   // [20, B]
    const float* __restrict__ k,   // [25]
    float* __restrict__ out,       // [B, 20]
    int B)
{
    int b = blockIdx.x * blockDim.x + threadIdx.x;
    if (b >= B) return;

    // Front-batched coalesced loads: row s is contiguous across threads.
    float c0  = C[(size_t)0  * B + b];
    float c1  = C[(size_t)1  * B + b];
    float c2  = C[(size_t)2  * B + b];
    float c3  = C[(size_t)3  * B + b];
    float c4  = C[(size_t)4  * B + b];
    float c5  = C[(size_t)5  * B + b];
    float c6  = C[(size_t)6  * B + b];
    float c8  = C[(size_t)8  * B + b];
    float c9  = C[(size_t)9  * B + b];
    float c10 = C[(size_t)10 * B + b];
    float c12 = C[(size_t)12 * B + b];
    float c13 = C[(size_t)13 * B + b];
    float c15 = C[(size_t)15 * B + b];
    float c16 = C[(size_t)16 * B + b];
    float c18 = C[(size_t)18 * B + b];
    float c19 = C[(size_t)19 * B + b];
    // rows 7, 11, 14, 17 are never read by any flux (only written as dy)

    // Fluxes (1-based naming to match the reference stoichiometry table)
    float r1  = __ldg(&k[0])  * c0;
    float r2  = __ldg(&k[1])  * c1  * c3;
    float r3  = __ldg(&k[2])  * c4  * c1;
    float r4  = __ldg(&k[3])  * c6;
    float r5  = __ldg(&k[4])  * c6;
    float r6  = __ldg(&k[5])  * c6  * c5;
    float r7  = __ldg(&k[6])  * c8;
    float r8  = __ldg(&k[7])  * c8  * c5;
    float r9  = __ldg(&k[8])  * c10 * c1;
    float r10 = __ldg(&k[9])  * c10 * c0;
    float r11 = __ldg(&k[10]) * c12;
    float r12 = __ldg(&k[11]) * c9  * c1;
    float r13 = __ldg(&k[12]) * c13;
    float r14 = __ldg(&k[13]) * c0  * c5;
    float r15 = __ldg(&k[14]) * c2;
    float r16 = __ldg(&k[15]) * c3;
    float r17 = __ldg(&k[16]) * c3;
    float r18 = __ldg(&k[17]) * c15;
    float r19 = __ldg(&k[18]) * c15;
    float r20 = __ldg(&k[19]) * c16 * c5;
    float r21 = __ldg(&k[20]) * c18;
    float r22 = __ldg(&k[21]) * c18;
    float r23 = __ldg(&k[22]) * c0  * c3;
    float r24 = __ldg(&k[23]) * c18 * c0;
    float r25 = __ldg(&k[24]) * c19;

    // dy, fully unrolled from the S matrix
    float dy0  = -r1 - r10 - r14 - r23 - r24 + r2 + r3 + r9 + r11 + r12 + r22 + r25;
    float dy1  = -r2 - r3 - r9 - r12 + r1 + r21;
    float dy2  = -r15 + r1 + r17 + r19 + r22;
    float dy3  = -r2 - r16 - r17 - r23 + r15;
    float dy4  = -r3 + 2.0f * r4 + r6 + r7 + r13 + r20;
    float dy5  = -r6 - r8 - r14 - r20 + r3 + 2.0f * r18;
    float dy6  = -r4 - r5 - r6 + r13;
    float dy7  =  r4 + r5 + r6 + r7;
    float dy8  = -r7 - r8;
    float dy9  = -r12 + r7 + r9;
    float dy10 = -r9 - r10 + r8 + r11;
    float dy11 =  r9;
    float dy12 = -r11 + r10;
    float dy13 = -r13 + r12;
    float dy14 =  r14;
    float dy15 = -r18 - r19 + r16;
    float dy16 = -r20;
    float dy17 =  r20;
    float dy18 = -r21 - r22 - r24 + r23 + r25;
    float dy19 = -r25 + r24;

    // 20 contiguous floats per thread (80 B, 16-aligned) -> 5x float4 stores.
    float4* o = reinterpret_cast<float4*>(out + (size_t)b * 20);
    o[0] = make_float4(dy0,  dy1,  dy2,  dy3);
    o[1] = make_float4(dy4,  dy5,  dy6,  dy7);
    o[2] = make_float4(dy8,  dy9,  dy10, dy11);
    o[3] = make_float4(dy12, dy13, dy14, dy15);
    o[4] = make_float4(dy16, dy17, dy18, dy19);
}

extern "C" void kernel_launch(void* const* d_in, const int* in_sizes, int n_in,
                              void* d_out, int out_size) {
    // metadata order: t [1], conc_in [20*B], k [25]
    const float* conc = (const float*)d_in[1];
    const float* k    = (const float*)d_in[2];
    float* out        = (float*)d_out;
    int B = in_sizes[1] / 20;

    int threads = 256;
    int blocks  = (B + threads - 1) / threads;
    pollu_kernel<<<blocks, threads>>>(conc, k, out, B);
}

// round 4
// speedup vs baseline: 1.2581x; 1.2581x over previous
#include <cuda_runtime.h>

// POLLU RHS: dy[b, 0:20] = S @ flux(b), flux_r = k_r * C[a_r,b] * C[b_r,b]
// R2: smem-transposed epilogue for fully coalesced float4 stores.
//
// Output layout [B, 20]. A block owns 256 consecutive columns -> 5120 floats
// = 1280 float4, contiguous in gmem. Each thread computes one column into
// registers, stages its 20 dys into smem (28-word column stride: STS.128
// conflict-free), then the block emits 1280 coalesced float4 STGs.

constexpr int TPB = 256;
constexpr int COL_STRIDE = 28;  // words per column in smem (16B-aligned, conflict-free STS.128)

__global__ void __launch_bounds__(TPB) pollu_kernel(
    const float* __restrict__ C,   // [20, B]
    const float* __restrict__ k,   // [25]
    float* __restrict__ out,       // [B, 20]
    int B)
{
    __shared__ float sm[TPB * COL_STRIDE];  // 28672 B

    const int tid  = threadIdx.x;
    const int base = blockIdx.x * TPB;
    const int b    = base + tid;

    if (b < B) {
        // Coalesced, streaming (use-once) row loads. Rows 7,11,14,17 unused.
        float c0  = __ldcs(&C[(size_t)0  * B + b]);
        float c1  = __ldcs(&C[(size_t)1  * B + b]);
        float c2  = __ldcs(&C[(size_t)2  * B + b]);
        float c3  = __ldcs(&C[(size_t)3  * B + b]);
        float c4  = __ldcs(&C[(size_t)4  * B + b]);
        float c5  = __ldcs(&C[(size_t)5  * B + b]);
        float c6  = __ldcs(&C[(size_t)6  * B + b]);
        float c8  = __ldcs(&C[(size_t)8  * B + b]);
        float c9  = __ldcs(&C[(size_t)9  * B + b]);
        float c10 = __ldcs(&C[(size_t)10 * B + b]);
        float c12 = __ldcs(&C[(size_t)12 * B + b]);
        float c13 = __ldcs(&C[(size_t)13 * B + b]);
        float c15 = __ldcs(&C[(size_t)15 * B + b]);
        float c16 = __ldcs(&C[(size_t)16 * B + b]);
        float c18 = __ldcs(&C[(size_t)18 * B + b]);
        float c19 = __ldcs(&C[(size_t)19 * B + b]);

        float r1  = __ldg(&k[0])  * c0;
        float r2  = __ldg(&k[1])  * c1  * c3;
        float r3  = __ldg(&k[2])  * c4  * c1;
        float r4  = __ldg(&k[3])  * c6;
        float r5  = __ldg(&k[4])  * c6;
        float r6  = __ldg(&k[5])  * c6  * c5;
        float r7  = __ldg(&k[6])  * c8;
        float r8  = __ldg(&k[7])  * c8  * c5;
        float r9  = __ldg(&k[8])  * c10 * c1;
        float r10 = __ldg(&k[9])  * c10 * c0;
        float r11 = __ldg(&k[10]) * c12;
        float r12 = __ldg(&k[11]) * c9  * c1;
        float r13 = __ldg(&k[12]) * c13;
        float r14 = __ldg(&k[13]) * c0  * c5;
        float r15 = __ldg(&k[14]) * c2;
        float r16 = __ldg(&k[15]) * c3;
        float r17 = __ldg(&k[16]) * c3;
        float r18 = __ldg(&k[17]) * c15;
        float r19 = __ldg(&k[18]) * c15;
        float r20 = __ldg(&k[19]) * c16 * c5;
        float r21 = __ldg(&k[20]) * c18;
        float r22 = __ldg(&k[21]) * c18;
        float r23 = __ldg(&k[22]) * c0  * c3;
        float r24 = __ldg(&k[23]) * c18 * c0;
        float r25 = __ldg(&k[24]) * c19;

        float dy0  = -r1 - r10 - r14 - r23 - r24 + r2 + r3 + r9 + r11 + r12 + r22 + r25;
        float dy1  = -r2 - r3 - r9 - r12 + r1 + r21;
        float dy2  = -r15 + r1 + r17 + r19 + r22;
        float dy3  = -r2 - r16 - r17 - r23 + r15;
        float dy4  = -r3 + 2.0f * r4 + r6 + r7 + r13 + r20;
        float dy5  = -r6 - r8 - r14 - r20 + r3 + 2.0f * r18;
        float dy6  = -r4 - r5 - r6 + r13;
        float dy7  =  r4 + r5 + r6 + r7;
        float dy8  = -r7 - r8;
        float dy9  = -r12 + r7 + r9;
        float dy10 = -r9 - r10 + r8 + r11;
        float dy11 =  r9;
        float dy12 = -r11 + r10;
        float dy13 = -r13 + r12;
        float dy14 =  r14;
        float dy15 = -r18 - r19 + r16;
        float dy16 = -r20;
        float dy17 =  r20;
        float dy18 = -r21 - r22 - r24 + r23 + r25;
        float dy19 = -r25 + r24;

        // Stage to smem: 5x STS.128 at 112B column stride (conflict-free).
        float4* s4 = reinterpret_cast<float4*>(&sm[tid * COL_STRIDE]);
        s4[0] = make_float4(dy0,  dy1,  dy2,  dy3);
        s4[1] = make_float4(dy4,  dy5,  dy6,  dy7);
        s4[2] = make_float4(dy8,  dy9,  dy10, dy11);
        s4[3] = make_float4(dy12, dy13, dy14, dy15);
        s4[4] = make_float4(dy16, dy17, dy18, dy19);
    }
    __syncthreads();

    // Coalesced epilogue: block writes min(TPB, B-base)*20 floats contiguously.
    int ncols = B - base;
    if (ncols > TPB) ncols = TPB;
    const int nf4 = ncols * 5;  // float4 count for this block

    float4* o4 = reinterpret_cast<float4*>(out + (size_t)base * 20);
    #pragma unroll
    for (int i = 0; i < 5; i++) {
        int f = tid + i * TPB;
        if (f < nf4) {
            // float4 f covers column f/5, species 4*(f%5)..4*(f%5)+3
            int col = f / 5;
            int s0  = (f - col * 5) * 4;
            float4 v = *reinterpret_cast<const float4*>(&sm[col * COL_STRIDE + s0]);
            __stcs(&o4[f], v);
        }
    }
}

extern "C" void kernel_launch(void* const* d_in, const int* in_sizes, int n_in,
                              void* d_out, int out_size) {
    // metadata order: t [1], conc_in [20*B], k [25]
    const float* conc = (const float*)d_in[1];
    const float* k    = (const float*)d_in[2];
    float* out        = (float*)d_out;
    int B = in_sizes[1] / 20;

    int blocks = (B + TPB - 1) / TPB;
    pollu_kernel<<<blocks, TPB>>>(conc, k, out, B);
}